// round 10
// baseline (speedup 1.0000x reference)
#include <cuda_runtime.h>
#include <cuda_bf16.h>
#include <cstdint>

// VectorQuantizer: N=65536 rows, D=256, K=1024 codes.
// Pass 1: packed-fp32 FFMA2 (fma.rn.f32x2) GEMM-argmin at 2x FFMA roofline.
//   BM=128 x BN=64 tiles; x tile transposed [d][row] with row-pairs packed;
//   e chunks duplicated (e,e) for direct 64-bit B operands. margin<0.02 -> flag.
// fix32: fp32 recompute of flagged rows; margin < 1e-3 -> fix64.
// fix64: compensated-fp32 (TwoProdFMA+TwoSum) dots, fp64 assembly,
//   TIE_EPS=7.5e-5 window pick-lowest (R6-calibrated semantics).

#define N_ROWS   65536
#define DIM      256
#define K_CODES  1024
#define FLAG_THR 0.02f
#define TIE_EPS  7.5e-5
#define AMB_CAP  16384
#define AMB2_CAP 4096
#define XSTR     132           // xs stride in floats (mult of 4 for 16B alignment)

typedef unsigned long long ull;

__device__ double g_loss_acc;
__device__ float  g_enorm[K_CODES];
__device__ double g_enorm_d[K_CODES];
__device__ float  g_eT[K_CODES * DIM];   // e transposed [k][d]
__device__ int    g_idx[N_ROWS];
__device__ int    g_amb[AMB_CAP];
__device__ int    g_amb_count;
__device__ int    g_amb2[AMB2_CAP];
__device__ int    g_amb2_count;

// smem float offsets
#define OFF_XS   0                         // 256 x 132 = 33792 f
#define OFF_ESD  33792                     // 64 d x 64 codes x float2 = 8192 f
#define OFF_SN   424984_GUARD              // (unused token guard)
#undef  OFF_SN
#define OFF_SNORM 41984                    // 64 f
#define OFF_RV   42048                     // 128*16 f
#define OFF_RS   44096                     // 128*16 f
#define OFF_RI   46144                     // 128*16 i
#define OFF_LRED 48192                     // 8 f
#define SMEM_FLOATS 48200
#define SMEM_BYTES  (SMEM_FLOATS * 4)

__device__ __forceinline__ void ffma2(ull& c, ull a, ull b) {
    asm("fma.rn.f32x2 %0, %1, %2, %0;" : "+l"(c) : "l"(a), "l"(b));
}
__device__ __forceinline__ ull dup2(float v) {
    unsigned u = __float_as_uint(v);
    return ((ull)u << 32) | u;
}
__device__ __forceinline__ float lo32(ull v) { return __uint_as_float((unsigned)v); }
__device__ __forceinline__ float hi32(ull v) { return __uint_as_float((unsigned)(v >> 32)); }

// ---------------------------------------------------------------------------
__global__ void vq_prep(const float* __restrict__ e) {
    int b = blockIdx.x;
    if (b < 256) {
        int d = b;
        for (int k = threadIdx.x; k < K_CODES; k += 256)
            g_eT[k * DIM + d] = e[d * K_CODES + k];
    } else {
        int k = (b - 256) * 256 + threadIdx.x;
        double s = 0.0;
        for (int d = 0; d < DIM; d++) {
            double v = (double)e[d * K_CODES + k];
            s += v * v;
        }
        g_enorm[k]   = (float)s;
        g_enorm_d[k] = s;
        if (b == 256 && threadIdx.x == 0) {
            g_loss_acc = 0.0; g_amb_count = 0; g_amb2_count = 0;
        }
    }
}

// ---------------------------------------------------------------------------
__global__ void __launch_bounds__(256) vq_main(const float* __restrict__ x,
                                               float* __restrict__ out) {
    extern __shared__ float sm[];
    float* xs    = sm + OFF_XS;        // [d][row], row-pairs packed
    ull*   esd   = (ull*)(sm + OFF_ESD); // [dl][code] duplicated (e,e)
    float* snorm = sm + OFF_SNORM;
    float* rv    = sm + OFF_RV;
    float* rs    = sm + OFF_RS;
    int*   ri    = (int*)(sm + OFF_RI);
    float* lred  = sm + OFF_LRED;

    const int tid  = threadIdx.x;
    const int lane = tid & 31;
    const int wid  = tid >> 5;
    const int tx   = tid & 15;
    const int ty   = tid >> 4;
    const int tx4  = tx * 4;
    const int ty8  = ty * 8;
    const int row0 = blockIdx.x * 128;
    const float* xblk = x + (size_t)row0 * DIM;

    // ---- transpose x tile into xs[d][row] ----
    #pragma unroll
    for (int it = 0; it < 32; it++) {
        int i  = it * 256 + tid;
        int r  = i >> 6;          // 0..127
        int c4 = i & 63;
        float4 v = ((const float4*)(xblk + (size_t)r * DIM))[c4];
        int d = c4 * 4;
        xs[(d + 0) * XSTR + r] = v.x;
        xs[(d + 1) * XSTR + r] = v.y;
        xs[(d + 2) * XSTR + r] = v.z;
        xs[(d + 3) * XSTR + r] = v.w;
    }

    float rb8[8], rs8[8]; int ri8[8];
    #pragma unroll
    for (int s2 = 0; s2 < 8; s2++) { rb8[s2] = 3.4e38f; rs8[s2] = 3.4e38f; ri8[s2] = 0; }

    ull acc[4][4];
    float4 pf[4];
    const int cl = tid & 63, dg = tid >> 6;

    // prefetch step 0: tile 0, dk 0
    {
        const float4* src = (const float4*)(g_eT + (size_t)cl * DIM + dg * 16);
        pf[0] = src[0]; pf[1] = src[1]; pf[2] = src[2]; pf[3] = src[3];
    }

    for (int s = 0; s < 64; s++) {
        const int tile = s >> 2, dk = s & 3;
        const int c0 = tile * 64;

        __syncthreads();
        // store prefetched chunk, duplicated
        #pragma unroll
        for (int q = 0; q < 4; q++) {
            int dl = dg * 16 + q * 4;
            esd[(dl + 0) * 64 + cl] = dup2(pf[q].x);
            esd[(dl + 1) * 64 + cl] = dup2(pf[q].y);
            esd[(dl + 2) * 64 + cl] = dup2(pf[q].z);
            esd[(dl + 3) * 64 + cl] = dup2(pf[q].w);
        }
        if (dk == 0 && tid < 64) snorm[tid] = g_enorm[c0 + tid];

        if (s + 1 < 64) {
            int t1 = (s + 1) >> 2, dk1 = (s + 1) & 3;
            const float4* src = (const float4*)(g_eT +
                (size_t)(t1 * 64 + cl) * DIM + dk1 * 64 + dg * 16);
            pf[0] = src[0]; pf[1] = src[1]; pf[2] = src[2]; pf[3] = src[3];
        }
        __syncthreads();

        if (dk == 0) {
            #pragma unroll
            for (int p = 0; p < 4; p++)
                #pragma unroll
                for (int j = 0; j < 4; j++) acc[p][j] = 0ull;
        }

        const float* xbase = xs + (dk * 64) * XSTR + ty8;
        #pragma unroll 8
        for (int dl = 0; dl < 64; dl++) {
            const ulonglong2* ap = (const ulonglong2*)(xbase + dl * XSTR);
            ulonglong2 a01 = ap[0];
            ulonglong2 a23 = ap[1];
            const ulonglong2* bp = (const ulonglong2*)(esd + dl * 64 + tx4);
            ulonglong2 b01 = bp[0];
            ulonglong2 b23 = bp[1];
            ffma2(acc[0][0], a01.x, b01.x); ffma2(acc[0][1], a01.x, b01.y);
            ffma2(acc[0][2], a01.x, b23.x); ffma2(acc[0][3], a01.x, b23.y);
            ffma2(acc[1][0], a01.y, b01.x); ffma2(acc[1][1], a01.y, b01.y);
            ffma2(acc[1][2], a01.y, b23.x); ffma2(acc[1][3], a01.y, b23.y);
            ffma2(acc[2][0], a23.x, b01.x); ffma2(acc[2][1], a23.x, b01.y);
            ffma2(acc[2][2], a23.x, b23.x); ffma2(acc[2][3], a23.x, b23.y);
            ffma2(acc[3][0], a23.y, b01.x); ffma2(acc[3][1], a23.y, b01.y);
            ffma2(acc[3][2], a23.y, b23.x); ffma2(acc[3][3], a23.y, b23.y);
        }

        if (dk == 3) {
            #pragma unroll
            for (int j = 0; j < 4; j++) {
                float n = snorm[tx4 + j];
                int  ci = c0 + tx4 + j;
                #pragma unroll
                for (int p = 0; p < 4; p++) {
                    float d0 = fmaf(-2.f, lo32(acc[p][j]), n);
                    float d1 = fmaf(-2.f, hi32(acc[p][j]), n);
                    int s0 = p * 2, s1 = p * 2 + 1;
                    if (d0 < rb8[s0]) { rs8[s0] = rb8[s0]; rb8[s0] = d0; ri8[s0] = ci; }
                    else if (d0 < rs8[s0]) rs8[s0] = d0;
                    if (d1 < rb8[s1]) { rs8[s1] = rb8[s1]; rb8[s1] = d1; ri8[s1] = ci; }
                    else if (d1 < rs8[s1]) rs8[s1] = d1;
                }
            }
        }
    }

    // ---- cross-tx reduce per row ----
    __syncthreads();
    #pragma unroll
    for (int s2 = 0; s2 < 8; s2++) {
        int row = ty8 + s2;
        rv[row * 16 + tx] = rb8[s2];
        rs[row * 16 + tx] = rs8[s2];
        ri[row * 16 + tx] = ri8[s2];
    }
    __syncthreads();
    if (tid < 128) {
        int row = tid;
        float b = 3.4e38f, sv = 3.4e38f; int bi = 0;
        #pragma unroll
        for (int t = 0; t < 16; t++) {
            float v  = rv[row * 16 + t];
            float s2 = rs[row * 16 + t];
            int   i2 = ri[row * 16 + t];
            if (v < b) { sv = fminf(b, s2); b = v; bi = i2; }
            else       { sv = fminf(sv, v); }
        }
        int grow = row0 + row;
        g_idx[grow] = bi;
        if (sv - b < FLAG_THR) {
            int slot = atomicAdd(&g_amb_count, 1);
            if (slot < AMB_CAP) g_amb[slot] = grow;
        }
        ri[row * 16] = bi;
    }
    __syncthreads();

    // ---- gather + straight-through output + loss (original fp32 from GMEM) ----
    float local = 0.f;
    #pragma unroll
    for (int rr = 0; rr < 16; rr++) {
        int row = wid * 16 + rr;
        int idx = ri[row * 16];
        const float* esrc = g_eT + (size_t)idx * DIM;
        const float* xrow = xblk + (size_t)row * DIM;
        float* orow = out + (size_t)(row0 + row) * DIM;
        #pragma unroll
        for (int kk = 0; kk < 8; kk++) {
            int d = kk * 32 + lane;
            float q  = esrc[d];
            float xv = xrow[d];
            float dq = q - xv;
            local += dq * dq;
            orow[d] = xv + dq;
        }
    }
    #pragma unroll
    for (int off = 16; off; off >>= 1)
        local += __shfl_xor_sync(0xffffffffu, local, off);
    if (lane == 0) lred[wid] = local;
    __syncthreads();
    if (tid == 0) {
        float ssum = 0.f;
        #pragma unroll
        for (int w = 0; w < 8; w++) ssum += lred[w];
        atomicAdd(&g_loss_acc, (double)ssum);
    }
}

// ---------------------------------------------------------------------------
// fix32: fp32 recompute of flagged rows. margin<1e-3 -> fix64, else patch.
__global__ void vq_fix32(const float* __restrict__ x, float* __restrict__ out) {
    __shared__ float  xr[DIM];
    __shared__ float  rb[256], rs[256];
    __shared__ int    rix[256];
    __shared__ double sdd[256];

    const int tid = threadIdx.x;
    int total = g_amb_count; if (total > AMB_CAP) total = AMB_CAP;

    for (int it = blockIdx.x; it < total; it += gridDim.x) {
        int row = g_amb[it];
        xr[tid] = x[(size_t)row * DIM + tid];
        __syncthreads();

        float s0 = 0.f, s1 = 0.f, s2 = 0.f, s3 = 0.f;
        const float* eb = g_eT + (size_t)tid * 4 * DIM;
        #pragma unroll 4
        for (int d = 0; d < DIM; d++) {
            float xv = xr[d];
            s0 = fmaf(xv, eb[d], s0);
            s1 = fmaf(xv, eb[DIM + d], s1);
            s2 = fmaf(xv, eb[2 * DIM + d], s2);
            s3 = fmaf(xv, eb[3 * DIM + d], s3);
        }
        float dj[4];
        dj[0] = fmaf(-2.f, s0, g_enorm[tid * 4 + 0]);
        dj[1] = fmaf(-2.f, s1, g_enorm[tid * 4 + 1]);
        dj[2] = fmaf(-2.f, s2, g_enorm[tid * 4 + 2]);
        dj[3] = fmaf(-2.f, s3, g_enorm[tid * 4 + 3]);

        float b = 3.4e38f, s = 3.4e38f; int bi = 0;
        #pragma unroll
        for (int j = 0; j < 4; j++) {
            int k = tid * 4 + j;
            if (dj[j] < b) { s = b; b = dj[j]; bi = k; }
            else if (dj[j] < s) s = dj[j];
        }
        rb[tid] = b; rs[tid] = s; rix[tid] = bi;
        __syncthreads();
        for (int off = 128; off; off >>= 1) {
            if (tid < off) {
                float b2 = rb[tid + off], s2v = rs[tid + off];
                int   i2 = rix[tid + off];
                float b1 = rb[tid], s1v = rs[tid];
                int   i1 = rix[tid];
                if (b2 < b1 || (b2 == b1 && i2 < i1)) {
                    rb[tid] = b2; rix[tid] = i2; rs[tid] = fminf(b1, s2v);
                } else {
                    rs[tid] = fminf(s1v, b2);
                }
            }
            __syncthreads();
        }
        float margin = rs[0] - rb[0];
        int newIdx = rix[0];
        int oldIdx = g_idx[row];
        __syncthreads();

        if (margin < 1e-3f) {
            if (tid == 0) {
                int slot = atomicAdd(&g_amb2_count, 1);
                if (slot < AMB2_CAP) g_amb2[slot] = row;
            }
        } else if (newIdx != oldIdx) {
            float xv = xr[tid];
            float qn = g_eT[(size_t)newIdx * DIM + tid];
            float qo = g_eT[(size_t)oldIdx * DIM + tid];
            out[(size_t)row * DIM + tid] = xv + (qn - xv);
            if (tid == 0) g_idx[row] = newIdx;
            double dn = (double)(qn - xv), dl = (double)(qo - xv);
            sdd[tid] = dn * dn - dl * dl;
            __syncthreads();
            for (int off = 128; off; off >>= 1) {
                if (tid < off) sdd[tid] += sdd[tid + off];
                __syncthreads();
            }
            if (tid == 0) atomicAdd(&g_loss_acc, sdd[0]);
        }
        __syncthreads();
    }
}

// ---------------------------------------------------------------------------
// fix64: compensated fp32 dots (error ~1e-10, fp64-equivalent at window scale),
// fp64 assembly + TIE_EPS window pick-lowest (R6-calibrated).
__global__ void vq_fix64(const float* __restrict__ x, float* __restrict__ out) {
    __shared__ float  xr[DIM];
    __shared__ double sdd[256];
    __shared__ double svv[256];
    __shared__ int    sii[256];
    __shared__ double s_minv;

    const int tid = threadIdx.x;
    int total = g_amb2_count; if (total > AMB2_CAP) total = AMB2_CAP;

    for (int it = blockIdx.x; it < total; it += gridDim.x) {
        int row = g_amb2[it];
        xr[tid] = x[(size_t)row * DIM + tid];
        __syncthreads();

        sdd[tid] = (double)xr[tid] * (double)xr[tid];
        __syncthreads();
        for (int off = 128; off; off >>= 1) {
            if (tid < off) sdd[tid] += sdd[tid + off];
            __syncthreads();
        }
        double xn = sdd[0];
        __syncthreads();

        // compensated dot per code (TwoProdFMA + TwoSum), 4-code ILP
        float s[4] = {0.f, 0.f, 0.f, 0.f};
        float c[4] = {0.f, 0.f, 0.f, 0.f};
        const float* eb = g_eT + (size_t)tid * 4 * DIM;
        for (int d = 0; d < DIM; d++) {
            float xv = xr[d];
            #pragma unroll
            for (int j = 0; j < 4; j++) {
                float ev = eb[j * DIM + d];
                float p  = xv * ev;
                float e1 = fmaf(xv, ev, -p);
                float t  = s[j] + p;
                float z  = t - s[j];
                float e2 = (s[j] - (t - z)) + (p - z);
                s[j] = t; c[j] += e1 + e2;
            }
        }
        double dist[4];
        #pragma unroll
        for (int j = 0; j < 4; j++)
            dist[j] = xn + g_enorm_d[tid * 4 + j]
                    - 2.0 * ((double)s[j] + (double)c[j]);

        double bv = 1e300; int bi = 0x7fffffff;
        #pragma unroll
        for (int j = 0; j < 4; j++) {
            int k = tid * 4 + j;
            if (dist[j] < bv || (dist[j] == bv && k < bi)) { bv = dist[j]; bi = k; }
        }
        svv[tid] = bv; sii[tid] = bi;
        __syncthreads();
        for (int off = 128; off; off >>= 1) {
            if (tid < off) {
                double v2 = svv[tid + off]; int i2 = sii[tid + off];
                if (v2 < svv[tid] || (v2 == svv[tid] && i2 < sii[tid])) {
                    svv[tid] = v2; sii[tid] = i2;
                }
            }
            __syncthreads();
        }
        if (tid == 0) s_minv = svv[0];
        __syncthreads();
        double minv = s_minv;

        int cand = 0x7fffffff;
        #pragma unroll
        for (int j = 0; j < 4; j++) {
            int k = tid * 4 + j;
            if (dist[j] <= minv + TIE_EPS && k < cand) cand = k;
        }
        sii[tid] = cand;
        __syncthreads();
        for (int off = 128; off; off >>= 1) {
            if (tid < off) { if (sii[tid + off] < sii[tid]) sii[tid] = sii[tid + off]; }
            __syncthreads();
        }
        int newIdx = sii[0];
        int oldIdx = g_idx[row];
        __syncthreads();

        if (newIdx != oldIdx) {
            float xv = xr[tid];
            float qn = g_eT[(size_t)newIdx * DIM + tid];
            float qo = g_eT[(size_t)oldIdx * DIM + tid];
            out[(size_t)row * DIM + tid] = xv + (qn - xv);
            double dn = (double)(qn - xv), dl = (double)(qo - xv);
            sdd[tid] = dn * dn - dl * dl;
            __syncthreads();
            for (int off = 128; off; off >>= 1) {
                if (tid < off) sdd[tid] += sdd[tid + off];
                __syncthreads();
            }
            if (tid == 0) atomicAdd(&g_loss_acc, sdd[0]);
        }
        __syncthreads();
    }
}

// ---------------------------------------------------------------------------
__global__ void vq_finish(float* __restrict__ out) {
    const double nd = (double)N_ROWS * (double)DIM;
    out[(size_t)N_ROWS * DIM] = (float)(1.25 * g_loss_acc / nd);
}

// ---------------------------------------------------------------------------
extern "C" void kernel_launch(void* const* d_in, const int* in_sizes, int n_in,
                              void* d_out, int out_size) {
    const float* x = (const float*)d_in[0];
    const float* e = (const float*)d_in[1];
    if (n_in >= 2 && in_sizes[0] == K_CODES * DIM && in_sizes[1] == N_ROWS * DIM) {
        e = (const float*)d_in[0];
        x = (const float*)d_in[1];
    }
    float* out = (float*)d_out;

    cudaFuncSetAttribute(vq_main, cudaFuncAttributeMaxDynamicSharedMemorySize, SMEM_BYTES);

    vq_prep<<<260, 256>>>(e);
    vq_main<<<N_ROWS / 128, 256, SMEM_BYTES>>>(x, out);
    vq_fix32<<<512, 256>>>(x, out);
    vq_fix64<<<128, 256>>>(x, out);
    if (out_size > N_ROWS * DIM) vq_finish<<<1, 1>>>(out);
}

// round 12
// speedup vs baseline: 2.0388x; 2.0388x over previous
#include <cuda_runtime.h>
#include <cuda_fp16.h>
#include <cstdint>

// VectorQuantizer: N=65536 rows, D=256, K=1024 codes.
// Pass 1: HFMA2 (half2) GEMM-argmin at 2x FFMA rate. x,e packed as half2
//   dim-pairs; 32-pair chunks accumulated in half2, promoted to fp32 per chunk.
//   margin < 0.75 -> flag.
// fix32: fp32 recompute, COALESCED e[d][c]; margin < 1e-3 -> fix64.
// fix64: compensated-fp32 exact dots + TIE_EPS=7.5e-5 window pick-lowest
//   (R6-calibrated semantics).

#define N_ROWS   65536
#define DIM      256
#define K_CODES  1024
#define BM       64
#define FLAG_THR 0.75f
#define TIE_EPS  7.5e-5
#define AMB_CAP  32768
#define AMB2_CAP 8192
#define ASTR2    68            // xs2 stride in half2

__device__ double  g_loss_acc;
__device__ float   g_enorm[K_CODES];
__device__ double  g_enorm_d[K_CODES];
__device__ float   g_eT[K_CODES * DIM];      // e transposed [k][d]
__device__ __half2 g_e2[128 * K_CODES];      // half2 packed [d2][k]
__device__ int     g_idx[N_ROWS];
__device__ int     g_amb[AMB_CAP];
__device__ int     g_amb_count;
__device__ int     g_amb2[AMB2_CAP];
__device__ int     g_amb2_count;

// smem FLOAT offsets (half2 = 4 BYTES = 1 float!)
#define OFF_XS2  0          // 128 d2 x 68 half2 = 8704 f
#define OFF_ES2  8704       // 32 d2 x 64 codes half2 = 2048 f
#define OFF_SN   10752      // 64 f
#define OFF_RV   10816      // 1024 f
#define OFF_RS   11840      // 1024 f
#define OFF_RI   12864      // 1024 i
#define OFF_LRED 13888      // 8 f
#define SMEM_FLOATS 13896
#define SMEM_BYTES  (SMEM_FLOATS * 4)       // 55584 B

// ---------------------------------------------------------------------------
// prep: 0-255 transpose eT; 256-259 norms+reset; 260-387 pack e2.
__global__ void vq_prep(const float* __restrict__ e) {
    int b = blockIdx.x;
    if (b < 256) {
        int d = b;
        for (int k = threadIdx.x; k < K_CODES; k += 256)
            g_eT[k * DIM + d] = e[d * K_CODES + k];
    } else if (b < 260) {
        int k = (b - 256) * 256 + threadIdx.x;
        double s = 0.0;
        for (int d = 0; d < DIM; d++) {
            double v = (double)e[d * K_CODES + k];
            s += v * v;
        }
        g_enorm[k]   = (float)s;
        g_enorm_d[k] = s;
        if (b == 256 && threadIdx.x == 0) {
            g_loss_acc = 0.0; g_amb_count = 0; g_amb2_count = 0;
        }
    } else {
        int d2 = b - 260;                    // 0..127
        for (int k = threadIdx.x; k < K_CODES; k += 256)
            g_e2[d2 * K_CODES + k] = __floats2half2_rn(
                e[(2 * d2) * K_CODES + k], e[(2 * d2 + 1) * K_CODES + k]);
    }
}

// ---------------------------------------------------------------------------
__global__ void __launch_bounds__(256) vq_main(const float* __restrict__ x,
                                               float* __restrict__ out) {
    extern __shared__ float sm[];
    __half2* xs2  = (__half2*)(sm + OFF_XS2);   // [d2][row]
    __half2* es2  = (__half2*)(sm + OFF_ES2);   // [d2local][code]
    float*   snorm = sm + OFF_SN;
    float*   rv   = sm + OFF_RV;
    float*   rs   = sm + OFF_RS;
    int*     ri   = (int*)(sm + OFF_RI);
    float*   lred = sm + OFF_LRED;

    const int tid  = threadIdx.x;
    const int lane = tid & 31;
    const int wid  = tid >> 5;
    const int tx   = tid & 15;
    const int ty   = tid >> 4;
    const int tx4  = tx * 4;
    const int ty4  = ty * 4;
    const int row0 = blockIdx.x * BM;
    const float* xblk = x + (size_t)row0 * DIM;

    // ---- stage x tile as half2 [d2][row] ----
    #pragma unroll
    for (int it = 0; it < 16; it++) {
        int i  = it * 256 + tid;
        int r  = i >> 6;          // 0..63
        int c4 = i & 63;
        float4 v = ((const float4*)(xblk + (size_t)r * DIM))[c4];
        int d2 = c4 * 2;
        xs2[d2 * ASTR2 + r]       = __floats2half2_rn(v.x, v.y);
        xs2[(d2 + 1) * ASTR2 + r] = __floats2half2_rn(v.z, v.w);
    }

    float bestv[4], secv[4];
    int   besti[4];
    #pragma unroll
    for (int i = 0; i < 4; i++) { bestv[i] = 3.4e38f; secv[i] = 3.4e38f; besti[i] = 0; }

    float facc[4][4];
    uint4 pf[2];
    const int d2l = tid >> 3, cg = tid & 7;   // d2l 0..31, cg 0..7

    // prefetch s=0 (tile 0, dk 0): 8 half2 (2 uint4) of codes cg*8..cg*8+7
    {
        const uint4* p = (const uint4*)&g_e2[(size_t)d2l * K_CODES + cg * 8];
        pf[0] = p[0]; pf[1] = p[1];
    }

    for (int s = 0; s < 64; s++) {
        const int tile = s >> 2, dk = s & 3;
        const int c0 = tile * 64;

        __syncthreads();
        {   // store prefetched chunk: es2[d2l][cg*8 .. cg*8+8)
            uint4* q = (uint4*)&es2[d2l * 64 + cg * 8];
            q[0] = pf[0]; q[1] = pf[1];
        }
        if (dk == 0 && tid < 64) snorm[tid] = g_enorm[c0 + tid];

        if (s + 1 < 64) {
            int t1 = (s + 1) >> 2, dk1 = (s + 1) & 3;
            const uint4* p = (const uint4*)&g_e2[
                (size_t)(dk1 * 32 + d2l) * K_CODES + t1 * 64 + cg * 8];
            pf[0] = p[0]; pf[1] = p[1];
        }
        __syncthreads();

        if (dk == 0) {
            #pragma unroll
            for (int i = 0; i < 4; i++)
                #pragma unroll
                for (int j = 0; j < 4; j++) facc[i][j] = 0.f;
        }

        __half2 acc2[4][4];
        #pragma unroll
        for (int i = 0; i < 4; i++)
            #pragma unroll
            for (int j = 0; j < 4; j++) acc2[i][j] = __floats2half2_rn(0.f, 0.f);

        const int dbase = dk * 32;
        #pragma unroll 8
        for (int d2 = 0; d2 < 32; d2++) {
            uint4 au = *(const uint4*)&xs2[(dbase + d2) * ASTR2 + ty4];
            uint4 bu = *(const uint4*)&es2[d2 * 64 + tx4];
            __half2 ax[4], bx[4];
            *(uint4*)ax = au;
            *(uint4*)bx = bu;
            #pragma unroll
            for (int i = 0; i < 4; i++)
                #pragma unroll
                for (int j = 0; j < 4; j++)
                    acc2[i][j] = __hfma2(ax[i], bx[j], acc2[i][j]);
        }

        // promote chunk sums to fp32
        #pragma unroll
        for (int i = 0; i < 4; i++)
            #pragma unroll
            for (int j = 0; j < 4; j++)
                facc[i][j] += __low2float(acc2[i][j]) + __high2float(acc2[i][j]);

        if (dk == 3) {
            #pragma unroll
            for (int j = 0; j < 4; j++) {
                float n = snorm[tx4 + j];
                int  ci = c0 + tx4 + j;
                #pragma unroll
                for (int i = 0; i < 4; i++) {
                    float dist = fmaf(-2.f, facc[i][j], n);
                    if (dist < bestv[i]) {
                        secv[i] = bestv[i]; bestv[i] = dist; besti[i] = ci;
                    } else if (dist < secv[i]) {
                        secv[i] = dist;
                    }
                }
            }
        }
    }

    // ---- cross-tx reduce per row ----
    __syncthreads();
    #pragma unroll
    for (int i = 0; i < 4; i++) {
        int row = ty4 + i;
        rv[row * 16 + tx] = bestv[i];
        rs[row * 16 + tx] = secv[i];
        ri[row * 16 + tx] = besti[i];
    }
    __syncthreads();
    if (tid < BM) {
        int row = tid;
        float m1v = 3.4e38f, m2v = 3.4e38f;
        int m1i = 0;
        #pragma unroll
        for (int t = 0; t < 16; t++) {
            float v  = rv[row * 16 + t];
            int   i2 = ri[row * 16 + t];
            float s2 = rs[row * 16 + t];
            if (v < m1v) {
                if (m1v < m2v) m2v = m1v;
                m1v = v; m1i = i2;
            } else if (v < m2v) m2v = v;
            if (s2 < m2v) m2v = s2;
        }
        m1i &= (K_CODES - 1);            // defensive
        int grow = row0 + row;
        g_idx[grow] = m1i;
        ri[row * 16] = m1i;
        if (!(m2v - m1v >= FLAG_THR)) {  // catches NaN too
            int slot = atomicAdd(&g_amb_count, 1);
            if (slot < AMB_CAP) g_amb[slot] = grow;
        }
    }
    __syncthreads();

    // ---- gather + straight-through output + loss (original fp32) ----
    float local = 0.f;
    #pragma unroll
    for (int rr = 0; rr < BM / 8; rr++) {
        int row = wid * 8 + rr;
        int idx = ri[row * 16] & (K_CODES - 1);
        const float* esrc = g_eT + (size_t)idx * DIM;
        const float* xrow = xblk + (size_t)row * DIM;
        float* orow = out + (size_t)(row0 + row) * DIM;
        #pragma unroll
        for (int kk = 0; kk < 8; kk++) {
            int d = kk * 32 + lane;
            float q  = esrc[d];
            float xv = xrow[d];
            float dq = q - xv;
            local += dq * dq;
            orow[d] = xv + dq;
        }
    }
    #pragma unroll
    for (int off = 16; off; off >>= 1)
        local += __shfl_xor_sync(0xffffffffu, local, off);
    if (lane == 0) lred[wid] = local;
    __syncthreads();
    if (tid == 0) {
        float ssum = 0.f;
        #pragma unroll
        for (int w = 0; w < 8; w++) ssum += lred[w];
        atomicAdd(&g_loss_acc, (double)ssum);
    }
}

// ---------------------------------------------------------------------------
// fix32: fp32 recompute with COALESCED e[d][c]. margin<1e-3 -> fix64.
__global__ void vq_fix32(const float* __restrict__ x, const float* __restrict__ e,
                         float* __restrict__ out) {
    __shared__ float  xr[DIM];
    __shared__ float  rb[256], rssh[256];
    __shared__ int    rix[256];
    __shared__ double sdd[256];

    const int tid = threadIdx.x;
    int total = g_amb_count; if (total > AMB_CAP) total = AMB_CAP;

    for (int it = blockIdx.x; it < total; it += gridDim.x) {
        int row = g_amb[it];
        xr[tid] = x[(size_t)row * DIM + tid];
        __syncthreads();

        float s0 = 0.f, s1 = 0.f, s2 = 0.f, s3 = 0.f;
        #pragma unroll 4
        for (int d = 0; d < DIM; d++) {
            float xv = xr[d];
            const float* ed = e + (size_t)d * K_CODES + tid;
            s0 = fmaf(xv, ed[0],   s0);
            s1 = fmaf(xv, ed[256], s1);
            s2 = fmaf(xv, ed[512], s2);
            s3 = fmaf(xv, ed[768], s3);
        }
        float dj[4];
        dj[0] = fmaf(-2.f, s0, g_enorm[tid]);
        dj[1] = fmaf(-2.f, s1, g_enorm[tid + 256]);
        dj[2] = fmaf(-2.f, s2, g_enorm[tid + 512]);
        dj[3] = fmaf(-2.f, s3, g_enorm[tid + 768]);

        float b = 3.4e38f, sv = 3.4e38f; int bi = 0;
        #pragma unroll
        for (int j = 0; j < 4; j++) {
            int k = tid + j * 256;
            if (dj[j] < b) { sv = b; b = dj[j]; bi = k; }
            else if (dj[j] < sv) sv = dj[j];
        }
        rb[tid] = b; rssh[tid] = sv; rix[tid] = bi;
        __syncthreads();
        for (int off = 128; off; off >>= 1) {
            if (tid < off) {
                float b2 = rb[tid + off], s2v = rssh[tid + off];
                int   i2 = rix[tid + off];
                float b1 = rb[tid], s1v = rssh[tid];
                int   i1 = rix[tid];
                if (b2 < b1 || (b2 == b1 && i2 < i1)) {
                    rb[tid] = b2; rix[tid] = i2; rssh[tid] = fminf(b1, s2v);
                } else {
                    rssh[tid] = fminf(s1v, b2);
                }
            }
            __syncthreads();
        }
        float margin = rssh[0] - rb[0];
        int newIdx = rix[0];
        int oldIdx = g_idx[row];
        __syncthreads();

        if (margin < 1e-3f) {
            if (tid == 0) {
                int slot = atomicAdd(&g_amb2_count, 1);
                if (slot < AMB2_CAP) g_amb2[slot] = row;
            }
        } else if (newIdx != oldIdx) {
            float xv = xr[tid];
            float qn = g_eT[(size_t)newIdx * DIM + tid];
            float qo = g_eT[(size_t)oldIdx * DIM + tid];
            out[(size_t)row * DIM + tid] = xv + (qn - xv);
            if (tid == 0) g_idx[row] = newIdx;
            double dn = (double)(qn - xv), dl = (double)(qo - xv);
            sdd[tid] = dn * dn - dl * dl;
            __syncthreads();
            for (int off = 128; off; off >>= 1) {
                if (tid < off) sdd[tid] += sdd[tid + off];
                __syncthreads();
            }
            if (tid == 0) atomicAdd(&g_loss_acc, sdd[0]);
        }
        __syncthreads();
    }
}

// ---------------------------------------------------------------------------
// fix64: compensated-fp32 exact dots (coalesced e[d][c]) + TIE_EPS window.
__global__ void vq_fix64(const float* __restrict__ x, const float* __restrict__ e,
                         float* __restrict__ out) {
    __shared__ float  xr[DIM];
    __shared__ double sdd[256];
    __shared__ double svv[256];
    __shared__ int    sii[256];
    __shared__ double s_minv;

    const int tid = threadIdx.x;
    int total = g_amb2_count; if (total > AMB2_CAP) total = AMB2_CAP;

    for (int it = blockIdx.x; it < total; it += gridDim.x) {
        int row = g_amb2[it];
        xr[tid] = x[(size_t)row * DIM + tid];
        __syncthreads();

        sdd[tid] = (double)xr[tid] * (double)xr[tid];
        __syncthreads();
        for (int off = 128; off; off >>= 1) {
            if (tid < off) sdd[tid] += sdd[tid + off];
            __syncthreads();
        }
        double xn = sdd[0];
        __syncthreads();

        float s[4] = {0.f, 0.f, 0.f, 0.f};
        float c[4] = {0.f, 0.f, 0.f, 0.f};
        for (int d = 0; d < DIM; d++) {
            float xv = xr[d];
            const float* ed = e + (size_t)d * K_CODES + tid;
            #pragma unroll
            for (int j = 0; j < 4; j++) {
                float ev = ed[j * 256];
                float p  = xv * ev;
                float e1 = fmaf(xv, ev, -p);
                float t  = s[j] + p;
                float z  = t - s[j];
                float e2 = (s[j] - (t - z)) + (p - z);
                s[j] = t; c[j] += e1 + e2;
            }
        }
        double dist[4];
        #pragma unroll
        for (int j = 0; j < 4; j++)
            dist[j] = xn + g_enorm_d[tid + j * 256]
                    - 2.0 * ((double)s[j] + (double)c[j]);

        double bv = 1e300; int bi = 0x7fffffff;
        #pragma unroll
        for (int j = 0; j < 4; j++) {
            int k = tid + j * 256;
            if (dist[j] < bv || (dist[j] == bv && k < bi)) { bv = dist[j]; bi = k; }
        }
        svv[tid] = bv; sii[tid] = bi;
        __syncthreads();
        for (int off = 128; off; off >>= 1) {
            if (tid < off) {
                double v2 = svv[tid + off]; int i2 = sii[tid + off];
                if (v2 < svv[tid] || (v2 == svv[tid] && i2 < sii[tid])) {
                    svv[tid] = v2; sii[tid] = i2;
                }
            }
            __syncthreads();
        }
        if (tid == 0) s_minv = svv[0];
        __syncthreads();
        double minv = s_minv;

        int cand = 0x7fffffff;
        #pragma unroll
        for (int j = 0; j < 4; j++) {
            int k = tid + j * 256;
            if (dist[j] <= minv + TIE_EPS && k < cand) cand = k;
        }
        sii[tid] = cand;
        __syncthreads();
        for (int off = 128; off; off >>= 1) {
            if (tid < off) { if (sii[tid + off] < sii[tid]) sii[tid] = sii[tid + off]; }
            __syncthreads();
        }
        int newIdx = sii[0] & (K_CODES - 1);
        int oldIdx = g_idx[row];
        __syncthreads();

        if (newIdx != oldIdx) {
            float xv = xr[tid];
            float qn = g_eT[(size_t)newIdx * DIM + tid];
            float qo = g_eT[(size_t)oldIdx * DIM + tid];
            out[(size_t)row * DIM + tid] = xv + (qn - xv);
            double dn = (double)(qn - xv), dl = (double)(qo - xv);
            sdd[tid] = dn * dn - dl * dl;
            __syncthreads();
            for (int off = 128; off; off >>= 1) {
                if (tid < off) sdd[tid] += sdd[tid + off];
                __syncthreads();
            }
            if (tid == 0) atomicAdd(&g_loss_acc, sdd[0]);
        }
        __syncthreads();
    }
}

// ---------------------------------------------------------------------------
__global__ void vq_finish(float* __restrict__ out) {
    const double nd = (double)N_ROWS * (double)DIM;
    out[(size_t)N_ROWS * DIM] = (float)(1.25 * g_loss_acc / nd);
}

// ---------------------------------------------------------------------------
extern "C" void kernel_launch(void* const* d_in, const int* in_sizes, int n_in,
                              void* d_out, int out_size) {
    const float* x = (const float*)d_in[0];
    const float* e = (const float*)d_in[1];
    if (n_in >= 2 && in_sizes[0] == K_CODES * DIM && in_sizes[1] == N_ROWS * DIM) {
        e = (const float*)d_in[0];
        x = (const float*)d_in[1];
    }
    float* out = (float*)d_out;

    cudaFuncSetAttribute(vq_main, cudaFuncAttributeMaxDynamicSharedMemorySize, SMEM_BYTES);

    vq_prep<<<388, 256>>>(e);
    vq_main<<<N_ROWS / BM, 256, SMEM_BYTES>>>(x, out);
    vq_fix32<<<1024, 256>>>(x, e, out);
    vq_fix64<<<256, 256>>>(x, e, out);
    if (out_size > N_ROWS * DIM) vq_finish<<<1, 1>>>(out);
}

// round 13
// speedup vs baseline: 2.2205x; 1.0891x over previous
#include <cuda_runtime.h>
#include <cuda_fp16.h>
#include <cstdint>

// VectorQuantizer: N=65536 rows, D=256, K=1024 codes.
// Pass 1: HFMA2 (half2) GEMM-argmin at 2x FFMA rate. margin < 0.5 -> flag.
// vq_fix: single exact repair — compensated-fp32 dots (float4-coalesced e[d][c],
//   MLP-unrolled) + TIE_EPS=7.5e-5 window pick-lowest (R6-calibrated semantics).

#define N_ROWS   65536
#define DIM      256
#define K_CODES  1024
#define BM       64
#define FLAG_THR 0.5f
#define TIE_EPS  7.5e-5
#define AMB_CAP  32768
#define ASTR2    68            // xs2 stride in half2

__device__ double  g_loss_acc;
__device__ float   g_enorm[K_CODES];
__device__ double  g_enorm_d[K_CODES];
__device__ float   g_eT[K_CODES * DIM];      // e transposed [k][d]
__device__ __half2 g_e2[128 * K_CODES];      // half2 packed [d2][k]
__device__ int     g_idx[N_ROWS];
__device__ int     g_amb[AMB_CAP];
__device__ int     g_amb_count;

// smem FLOAT offsets (half2 = 4 bytes = 1 float)
#define OFF_XS2  0          // 128 d2 x 68 half2 = 8704 f
#define OFF_ES2  8704       // 32 d2 x 64 codes half2 = 2048 f
#define OFF_SN   10752      // 64 f
#define OFF_RV   10816      // 1024 f
#define OFF_RS   11840      // 1024 f
#define OFF_RI   12864      // 1024 i
#define OFF_LRED 13888      // 8 f
#define SMEM_FLOATS 13896
#define SMEM_BYTES  (SMEM_FLOATS * 4)

// ---------------------------------------------------------------------------
// prep: 0-255 transpose eT; 256-259 norms+reset; 260-387 pack e2.
__global__ void vq_prep(const float* __restrict__ e) {
    int b = blockIdx.x;
    if (b < 256) {
        int d = b;
        for (int k = threadIdx.x; k < K_CODES; k += 256)
            g_eT[k * DIM + d] = e[d * K_CODES + k];
    } else if (b < 260) {
        int k = (b - 256) * 256 + threadIdx.x;
        double s = 0.0;
        for (int d = 0; d < DIM; d++) {
            double v = (double)e[d * K_CODES + k];
            s += v * v;
        }
        g_enorm[k]   = (float)s;
        g_enorm_d[k] = s;
        if (b == 256 && threadIdx.x == 0) {
            g_loss_acc = 0.0; g_amb_count = 0;
        }
    } else {
        int d2 = b - 260;                    // 0..127
        for (int k = threadIdx.x; k < K_CODES; k += 256)
            g_e2[d2 * K_CODES + k] = __floats2half2_rn(
                e[(2 * d2) * K_CODES + k], e[(2 * d2 + 1) * K_CODES + k]);
    }
}

// ---------------------------------------------------------------------------
__global__ void __launch_bounds__(256) vq_main(const float* __restrict__ x,
                                               float* __restrict__ out) {
    extern __shared__ float sm[];
    __half2* xs2  = (__half2*)(sm + OFF_XS2);   // [d2][row]
    __half2* es2  = (__half2*)(sm + OFF_ES2);   // [d2local][code]
    float*   snorm = sm + OFF_SN;
    float*   rv   = sm + OFF_RV;
    float*   rs   = sm + OFF_RS;
    int*     ri   = (int*)(sm + OFF_RI);
    float*   lred = sm + OFF_LRED;

    const int tid  = threadIdx.x;
    const int lane = tid & 31;
    const int wid  = tid >> 5;
    const int tx   = tid & 15;
    const int ty   = tid >> 4;
    const int tx4  = tx * 4;
    const int ty4  = ty * 4;
    const int row0 = blockIdx.x * BM;
    const float* xblk = x + (size_t)row0 * DIM;

    // ---- stage x tile as half2 [d2][row] ----
    #pragma unroll
    for (int it = 0; it < 16; it++) {
        int i  = it * 256 + tid;
        int r  = i >> 6;
        int c4 = i & 63;
        float4 v = ((const float4*)(xblk + (size_t)r * DIM))[c4];
        int d2 = c4 * 2;
        xs2[d2 * ASTR2 + r]       = __floats2half2_rn(v.x, v.y);
        xs2[(d2 + 1) * ASTR2 + r] = __floats2half2_rn(v.z, v.w);
    }

    float bestv[4], secv[4];
    int   besti[4];
    #pragma unroll
    for (int i = 0; i < 4; i++) { bestv[i] = 3.4e38f; secv[i] = 3.4e38f; besti[i] = 0; }

    float facc[4][4];
    uint4 pf[2];
    const int d2l = tid >> 3, cg = tid & 7;

    {
        const uint4* p = (const uint4*)&g_e2[(size_t)d2l * K_CODES + cg * 8];
        pf[0] = p[0]; pf[1] = p[1];
    }

    for (int s = 0; s < 64; s++) {
        const int tile = s >> 2, dk = s & 3;
        const int c0 = tile * 64;

        __syncthreads();
        {
            uint4* q = (uint4*)&es2[d2l * 64 + cg * 8];
            q[0] = pf[0]; q[1] = pf[1];
        }
        if (dk == 0 && tid < 64) snorm[tid] = g_enorm[c0 + tid];

        if (s + 1 < 64) {
            int t1 = (s + 1) >> 2, dk1 = (s + 1) & 3;
            const uint4* p = (const uint4*)&g_e2[
                (size_t)(dk1 * 32 + d2l) * K_CODES + t1 * 64 + cg * 8];
            pf[0] = p[0]; pf[1] = p[1];
        }
        __syncthreads();

        if (dk == 0) {
            #pragma unroll
            for (int i = 0; i < 4; i++)
                #pragma unroll
                for (int j = 0; j < 4; j++) facc[i][j] = 0.f;
        }

        __half2 acc2[4][4];
        #pragma unroll
        for (int i = 0; i < 4; i++)
            #pragma unroll
            for (int j = 0; j < 4; j++) acc2[i][j] = __floats2half2_rn(0.f, 0.f);

        const int dbase = dk * 32;
        #pragma unroll 8
        for (int d2 = 0; d2 < 32; d2++) {
            uint4 au = *(const uint4*)&xs2[(dbase + d2) * ASTR2 + ty4];
            uint4 bu = *(const uint4*)&es2[d2 * 64 + tx4];
            __half2 ax[4], bx[4];
            *(uint4*)ax = au;
            *(uint4*)bx = bu;
            #pragma unroll
            for (int i = 0; i < 4; i++)
                #pragma unroll
                for (int j = 0; j < 4; j++)
                    acc2[i][j] = __hfma2(ax[i], bx[j], acc2[i][j]);
        }

        #pragma unroll
        for (int i = 0; i < 4; i++)
            #pragma unroll
            for (int j = 0; j < 4; j++)
                facc[i][j] += __low2float(acc2[i][j]) + __high2float(acc2[i][j]);

        if (dk == 3) {
            #pragma unroll
            for (int j = 0; j < 4; j++) {
                float n = snorm[tx4 + j];
                int  ci = c0 + tx4 + j;
                #pragma unroll
                for (int i = 0; i < 4; i++) {
                    float dist = fmaf(-2.f, facc[i][j], n);
                    if (dist < bestv[i]) {
                        secv[i] = bestv[i]; bestv[i] = dist; besti[i] = ci;
                    } else if (dist < secv[i]) {
                        secv[i] = dist;
                    }
                }
            }
        }
    }

    // ---- cross-tx reduce per row ----
    __syncthreads();
    #pragma unroll
    for (int i = 0; i < 4; i++) {
        int row = ty4 + i;
        rv[row * 16 + tx] = bestv[i];
        rs[row * 16 + tx] = secv[i];
        ri[row * 16 + tx] = besti[i];
    }
    __syncthreads();
    if (tid < BM) {
        int row = tid;
        float m1v = 3.4e38f, m2v = 3.4e38f;
        int m1i = 0;
        #pragma unroll
        for (int t = 0; t < 16; t++) {
            float v  = rv[row * 16 + t];
            int   i2 = ri[row * 16 + t];
            float s2 = rs[row * 16 + t];
            if (v < m1v) {
                if (m1v < m2v) m2v = m1v;
                m1v = v; m1i = i2;
            } else if (v < m2v) m2v = v;
            if (s2 < m2v) m2v = s2;
        }
        m1i &= (K_CODES - 1);
        int grow = row0 + row;
        g_idx[grow] = m1i;
        ri[row * 16] = m1i;
        if (!(m2v - m1v >= FLAG_THR)) {   // NaN-safe
            int slot = atomicAdd(&g_amb_count, 1);
            if (slot < AMB_CAP) g_amb[slot] = grow;
        }
    }
    __syncthreads();

    // ---- gather + straight-through output + loss (original fp32) ----
    float local = 0.f;
    #pragma unroll
    for (int rr = 0; rr < BM / 8; rr++) {
        int row = wid * 8 + rr;
        int idx = ri[row * 16] & (K_CODES - 1);
        const float* esrc = g_eT + (size_t)idx * DIM;
        const float* xrow = xblk + (size_t)row * DIM;
        float* orow = out + (size_t)(row0 + row) * DIM;
        #pragma unroll
        for (int kk = 0; kk < 8; kk++) {
            int d = kk * 32 + lane;
            float q  = esrc[d];
            float xv = xrow[d];
            float dq = q - xv;
            local += dq * dq;
            orow[d] = xv + dq;
        }
    }
    #pragma unroll
    for (int off = 16; off; off >>= 1)
        local += __shfl_xor_sync(0xffffffffu, local, off);
    if (lane == 0) lred[wid] = local;
    __syncthreads();
    if (tid == 0) {
        float ssum = 0.f;
        #pragma unroll
        for (int w = 0; w < 8; w++) ssum += lred[w];
        atomicAdd(&g_loss_acc, (double)ssum);
    }
}

// ---------------------------------------------------------------------------
// vq_fix: single exact repair. Compensated-fp32 dots (codes tid*4..tid*4+3 via
// one float4/d, unrolled for MLP) + TIE_EPS window pick-lowest; patch out+loss.
__global__ void __launch_bounds__(256) vq_fix(const float* __restrict__ x,
                                              const float* __restrict__ e,
                                              float* __restrict__ out) {
    __shared__ float  xr[DIM];
    __shared__ double sdd[256];
    __shared__ double svv[256];
    __shared__ int    sii[256];
    __shared__ double s_minv;

    const int tid = threadIdx.x;
    int total = g_amb_count; if (total > AMB_CAP) total = AMB_CAP;

    for (int it = blockIdx.x; it < total; it += gridDim.x) {
        int row = g_amb[it];
        xr[tid] = x[(size_t)row * DIM + tid];
        __syncthreads();

        sdd[tid] = (double)xr[tid] * (double)xr[tid];
        __syncthreads();
        for (int off = 128; off; off >>= 1) {
            if (tid < off) sdd[tid] += sdd[tid + off];
            __syncthreads();
        }
        double xn = sdd[0];
        __syncthreads();

        // compensated dots for codes tid*4+j (coalesced float4 per d)
        float s[4] = {0.f, 0.f, 0.f, 0.f};
        float c[4] = {0.f, 0.f, 0.f, 0.f};
        const float* ebase = e + (size_t)tid * 4;
        #pragma unroll 4
        for (int d = 0; d < DIM; d++) {
            float xv = xr[d];
            float4 ev = *(const float4*)(ebase + (size_t)d * K_CODES);
            float evs[4] = {ev.x, ev.y, ev.z, ev.w};
            #pragma unroll
            for (int j = 0; j < 4; j++) {
                float p  = xv * evs[j];
                float e1 = fmaf(xv, evs[j], -p);
                float t  = s[j] + p;
                float z  = t - s[j];
                float e2 = (s[j] - (t - z)) + (p - z);
                s[j] = t; c[j] += e1 + e2;
            }
        }
        double dist[4];
        #pragma unroll
        for (int j = 0; j < 4; j++)
            dist[j] = xn + g_enorm_d[tid * 4 + j]
                    - 2.0 * ((double)s[j] + (double)c[j]);

        double bv = 1e300; int bi = 0x7fffffff;
        #pragma unroll
        for (int j = 0; j < 4; j++) {
            int k = tid * 4 + j;
            if (dist[j] < bv || (dist[j] == bv && k < bi)) { bv = dist[j]; bi = k; }
        }
        svv[tid] = bv; sii[tid] = bi;
        __syncthreads();
        for (int off = 128; off; off >>= 1) {
            if (tid < off) {
                double v2 = svv[tid + off]; int i2 = sii[tid + off];
                if (v2 < svv[tid] || (v2 == svv[tid] && i2 < sii[tid])) {
                    svv[tid] = v2; sii[tid] = i2;
                }
            }
            __syncthreads();
        }
        if (tid == 0) s_minv = svv[0];
        __syncthreads();
        double minv = s_minv;

        // tie window (R6-calibrated): lowest index with dist <= min + TIE_EPS
        int cand = 0x7fffffff;
        #pragma unroll
        for (int j = 0; j < 4; j++) {
            int k = tid * 4 + j;
            if (dist[j] <= minv + TIE_EPS && k < cand) cand = k;
        }
        sii[tid] = cand;
        __syncthreads();
        for (int off = 128; off; off >>= 1) {
            if (tid < off) { if (sii[tid + off] < sii[tid]) sii[tid] = sii[tid + off]; }
            __syncthreads();
        }
        int newIdx = sii[0] & (K_CODES - 1);
        int oldIdx = g_idx[row];
        __syncthreads();

        if (newIdx != oldIdx) {     // uniform across block
            float xv = xr[tid];
            float qn = g_eT[(size_t)newIdx * DIM + tid];
            float qo = g_eT[(size_t)oldIdx * DIM + tid];
            out[(size_t)row * DIM + tid] = xv + (qn - xv);
            double dn = (double)(qn - xv), dl = (double)(qo - xv);
            sdd[tid] = dn * dn - dl * dl;
            __syncthreads();
            for (int off = 128; off; off >>= 1) {
                if (tid < off) sdd[tid] += sdd[tid + off];
                __syncthreads();
            }
            if (tid == 0) atomicAdd(&g_loss_acc, sdd[0]);
        }
        __syncthreads();
    }
}

// ---------------------------------------------------------------------------
__global__ void vq_finish(float* __restrict__ out) {
    const double nd = (double)N_ROWS * (double)DIM;
    out[(size_t)N_ROWS * DIM] = (float)(1.25 * g_loss_acc / nd);
}

// ---------------------------------------------------------------------------
extern "C" void kernel_launch(void* const* d_in, const int* in_sizes, int n_in,
                              void* d_out, int out_size) {
    const float* x = (const float*)d_in[0];
    const float* e = (const float*)d_in[1];
    if (n_in >= 2 && in_sizes[0] == K_CODES * DIM && in_sizes[1] == N_ROWS * DIM) {
        e = (const float*)d_in[0];
        x = (const float*)d_in[1];
    }
    float* out = (float*)d_out;

    cudaFuncSetAttribute(vq_main, cudaFuncAttributeMaxDynamicSharedMemorySize, SMEM_BYTES);

    vq_prep<<<388, 256>>>(e);
    vq_main<<<N_ROWS / BM, 256, SMEM_BYTES>>>(x, out);
    vq_fix<<<2048, 256>>>(x, e, out);
    if (out_size > N_ROWS * DIM) vq_finish<<<1, 1>>>(out);
}

// round 14
// speedup vs baseline: 2.7532x; 1.2399x over previous
#include <cuda_runtime.h>
#include <cuda_fp16.h>
#include <cstdint>

// VectorQuantizer: N=65536 rows, D=256, K=1024 codes.
// Pass 1: HFMA2 (half2) GEMM-argmin at 2x FFMA rate. margin < 0.5 -> flag.
// vq_fix (two-tier, single kernel): quick fp32 dots (float4-coalesced, MLP-8)
//   -> block margin; if margin < 1e-3, compensated-fp32 exact dots +
//   TIE_EPS=7.5e-5 window pick-lowest (R6-calibrated). Patch out + loss.

#define N_ROWS   65536
#define DIM      256
#define K_CODES  1024
#define BM       64
#define FLAG_THR 0.5f
#define TIE_EPS  7.5e-5
#define AMB_CAP  32768
#define ASTR2    68            // xs2 stride in half2

__device__ double  g_loss_acc;
__device__ float   g_enorm[K_CODES];
__device__ double  g_enorm_d[K_CODES];
__device__ float   g_eT[K_CODES * DIM];      // e transposed [k][d]
__device__ __half2 g_e2[128 * K_CODES];      // half2 packed [d2][k]
__device__ int     g_idx[N_ROWS];
__device__ int     g_amb[AMB_CAP];
__device__ int     g_amb_count;

// smem FLOAT offsets (half2 = 4 bytes = 1 float)
#define OFF_XS2  0          // 128 d2 x 68 half2 = 8704 f
#define OFF_ES2  8704       // 32 d2 x 64 codes half2 = 2048 f
#define OFF_SN   10752      // 64 f
#define OFF_RV   10816      // 1024 f
#define OFF_RS   11840      // 1024 f
#define OFF_RI   12864      // 1024 i
#define OFF_LRED 13888      // 8 f
#define SMEM_FLOATS 13896
#define SMEM_BYTES  (SMEM_FLOATS * 4)

// ---------------------------------------------------------------------------
// prep: 0-255 transpose eT; 256-259 norms+reset; 260-387 pack e2.
__global__ void vq_prep(const float* __restrict__ e) {
    int b = blockIdx.x;
    if (b < 256) {
        int d = b;
        for (int k = threadIdx.x; k < K_CODES; k += 256)
            g_eT[k * DIM + d] = e[d * K_CODES + k];
    } else if (b < 260) {
        int k = (b - 256) * 256 + threadIdx.x;
        double s = 0.0;
        for (int d = 0; d < DIM; d++) {
            double v = (double)e[d * K_CODES + k];
            s += v * v;
        }
        g_enorm[k]   = (float)s;
        g_enorm_d[k] = s;
        if (b == 256 && threadIdx.x == 0) {
            g_loss_acc = 0.0; g_amb_count = 0;
        }
    } else {
        int d2 = b - 260;                    // 0..127
        for (int k = threadIdx.x; k < K_CODES; k += 256)
            g_e2[d2 * K_CODES + k] = __floats2half2_rn(
                e[(2 * d2) * K_CODES + k], e[(2 * d2 + 1) * K_CODES + k]);
    }
}

// ---------------------------------------------------------------------------
__global__ void __launch_bounds__(256) vq_main(const float* __restrict__ x,
                                               float* __restrict__ out) {
    extern __shared__ float sm[];
    __half2* xs2  = (__half2*)(sm + OFF_XS2);   // [d2][row]
    __half2* es2  = (__half2*)(sm + OFF_ES2);   // [d2local][code]
    float*   snorm = sm + OFF_SN;
    float*   rv   = sm + OFF_RV;
    float*   rs   = sm + OFF_RS;
    int*     ri   = (int*)(sm + OFF_RI);
    float*   lred = sm + OFF_LRED;

    const int tid  = threadIdx.x;
    const int lane = tid & 31;
    const int wid  = tid >> 5;
    const int tx   = tid & 15;
    const int ty   = tid >> 4;
    const int tx4  = tx * 4;
    const int ty4  = ty * 4;
    const int row0 = blockIdx.x * BM;
    const float* xblk = x + (size_t)row0 * DIM;

    // ---- stage x tile as half2 [d2][row] ----
    #pragma unroll
    for (int it = 0; it < 16; it++) {
        int i  = it * 256 + tid;
        int r  = i >> 6;
        int c4 = i & 63;
        float4 v = ((const float4*)(xblk + (size_t)r * DIM))[c4];
        int d2 = c4 * 2;
        xs2[d2 * ASTR2 + r]       = __floats2half2_rn(v.x, v.y);
        xs2[(d2 + 1) * ASTR2 + r] = __floats2half2_rn(v.z, v.w);
    }

    float bestv[4], secv[4];
    int   besti[4];
    #pragma unroll
    for (int i = 0; i < 4; i++) { bestv[i] = 3.4e38f; secv[i] = 3.4e38f; besti[i] = 0; }

    float facc[4][4];
    uint4 pf[2];
    const int d2l = tid >> 3, cg = tid & 7;

    {
        const uint4* p = (const uint4*)&g_e2[(size_t)d2l * K_CODES + cg * 8];
        pf[0] = p[0]; pf[1] = p[1];
    }

    for (int s = 0; s < 64; s++) {
        const int tile = s >> 2, dk = s & 3;
        const int c0 = tile * 64;

        __syncthreads();
        {
            uint4* q = (uint4*)&es2[d2l * 64 + cg * 8];
            q[0] = pf[0]; q[1] = pf[1];
        }
        if (dk == 0 && tid < 64) snorm[tid] = g_enorm[c0 + tid];

        if (s + 1 < 64) {
            int t1 = (s + 1) >> 2, dk1 = (s + 1) & 3;
            const uint4* p = (const uint4*)&g_e2[
                (size_t)(dk1 * 32 + d2l) * K_CODES + t1 * 64 + cg * 8];
            pf[0] = p[0]; pf[1] = p[1];
        }
        __syncthreads();

        if (dk == 0) {
            #pragma unroll
            for (int i = 0; i < 4; i++)
                #pragma unroll
                for (int j = 0; j < 4; j++) facc[i][j] = 0.f;
        }

        __half2 acc2[4][4];
        #pragma unroll
        for (int i = 0; i < 4; i++)
            #pragma unroll
            for (int j = 0; j < 4; j++) acc2[i][j] = __floats2half2_rn(0.f, 0.f);

        const int dbase = dk * 32;
        #pragma unroll 8
        for (int d2 = 0; d2 < 32; d2++) {
            uint4 au = *(const uint4*)&xs2[(dbase + d2) * ASTR2 + ty4];
            uint4 bu = *(const uint4*)&es2[d2 * 64 + tx4];
            __half2 ax[4], bx[4];
            *(uint4*)ax = au;
            *(uint4*)bx = bu;
            #pragma unroll
            for (int i = 0; i < 4; i++)
                #pragma unroll
                for (int j = 0; j < 4; j++)
                    acc2[i][j] = __hfma2(ax[i], bx[j], acc2[i][j]);
        }

        #pragma unroll
        for (int i = 0; i < 4; i++)
            #pragma unroll
            for (int j = 0; j < 4; j++)
                facc[i][j] += __low2float(acc2[i][j]) + __high2float(acc2[i][j]);

        if (dk == 3) {
            #pragma unroll
            for (int j = 0; j < 4; j++) {
                float n = snorm[tx4 + j];
                int  ci = c0 + tx4 + j;
                #pragma unroll
                for (int i = 0; i < 4; i++) {
                    float dist = fmaf(-2.f, facc[i][j], n);
                    if (dist < bestv[i]) {
                        secv[i] = bestv[i]; bestv[i] = dist; besti[i] = ci;
                    } else if (dist < secv[i]) {
                        secv[i] = dist;
                    }
                }
            }
        }
    }

    // ---- cross-tx reduce per row ----
    __syncthreads();
    #pragma unroll
    for (int i = 0; i < 4; i++) {
        int row = ty4 + i;
        rv[row * 16 + tx] = bestv[i];
        rs[row * 16 + tx] = secv[i];
        ri[row * 16 + tx] = besti[i];
    }
    __syncthreads();
    if (tid < BM) {
        int row = tid;
        float m1v = 3.4e38f, m2v = 3.4e38f;
        int m1i = 0;
        #pragma unroll
        for (int t = 0; t < 16; t++) {
            float v  = rv[row * 16 + t];
            int   i2 = ri[row * 16 + t];
            float s2 = rs[row * 16 + t];
            if (v < m1v) {
                if (m1v < m2v) m2v = m1v;
                m1v = v; m1i = i2;
            } else if (v < m2v) m2v = v;
            if (s2 < m2v) m2v = s2;
        }
        m1i &= (K_CODES - 1);
        int grow = row0 + row;
        g_idx[grow] = m1i;
        ri[row * 16] = m1i;
        if (!(m2v - m1v >= FLAG_THR)) {   // NaN-safe
            int slot = atomicAdd(&g_amb_count, 1);
            if (slot < AMB_CAP) g_amb[slot] = grow;
        }
    }
    __syncthreads();

    // ---- gather + straight-through output + loss (original fp32) ----
    float local = 0.f;
    #pragma unroll
    for (int rr = 0; rr < BM / 8; rr++) {
        int row = wid * 8 + rr;
        int idx = ri[row * 16] & (K_CODES - 1);
        const float* esrc = g_eT + (size_t)idx * DIM;
        const float* xrow = xblk + (size_t)row * DIM;
        float* orow = out + (size_t)(row0 + row) * DIM;
        #pragma unroll
        for (int kk = 0; kk < 8; kk++) {
            int d = kk * 32 + lane;
            float q  = esrc[d];
            float xv = xrow[d];
            float dq = q - xv;
            local += dq * dq;
            orow[d] = xv + dq;
        }
    }
    #pragma unroll
    for (int off = 16; off; off >>= 1)
        local += __shfl_xor_sync(0xffffffffu, local, off);
    if (lane == 0) lred[wid] = local;
    __syncthreads();
    if (tid == 0) {
        float ssum = 0.f;
        #pragma unroll
        for (int w = 0; w < 8; w++) ssum += lred[w];
        atomicAdd(&g_loss_acc, (double)ssum);
    }
}

// ---------------------------------------------------------------------------
// vq_fix (two-tier): quick fp32 dots -> margin; compensated+window only when
// margin < 1e-3. Codes tid*4..tid*4+3 via one float4/d (coalesced, MLP-8).
__global__ void __launch_bounds__(256) vq_fix(const float* __restrict__ x,
                                              const float* __restrict__ e,
                                              float* __restrict__ out) {
    __shared__ float  xr[DIM];
    __shared__ float  frb[256], frs[256];
    __shared__ int    fri[256];
    __shared__ double sdd[256];
    __shared__ double svv[256];
    __shared__ int    sii[256];
    __shared__ double s_minv;

    const int tid = threadIdx.x;
    int total = g_amb_count; if (total > AMB_CAP) total = AMB_CAP;

    for (int it = blockIdx.x; it < total; it += gridDim.x) {
        int row = g_amb[it];
        xr[tid] = x[(size_t)row * DIM + tid];
        __syncthreads();

        // ---- tier 1: quick fp32 dots (codes tid*4+j) ----
        float q0 = 0.f, q1 = 0.f, q2 = 0.f, q3 = 0.f;
        const float* ebase = e + (size_t)tid * 4;
        #pragma unroll 8
        for (int d = 0; d < DIM; d++) {
            float xv = xr[d];
            float4 ev = *(const float4*)(ebase + (size_t)d * K_CODES);
            q0 = fmaf(xv, ev.x, q0);
            q1 = fmaf(xv, ev.y, q1);
            q2 = fmaf(xv, ev.z, q2);
            q3 = fmaf(xv, ev.w, q3);
        }
        float dj[4];
        dj[0] = fmaf(-2.f, q0, g_enorm[tid * 4 + 0]);
        dj[1] = fmaf(-2.f, q1, g_enorm[tid * 4 + 1]);
        dj[2] = fmaf(-2.f, q2, g_enorm[tid * 4 + 2]);
        dj[3] = fmaf(-2.f, q3, g_enorm[tid * 4 + 3]);

        float b = 3.4e38f, sv = 3.4e38f; int bi = 0;
        #pragma unroll
        for (int j = 0; j < 4; j++) {
            int k = tid * 4 + j;
            if (dj[j] < b) { sv = b; b = dj[j]; bi = k; }
            else if (dj[j] < sv) sv = dj[j];
        }
        frb[tid] = b; frs[tid] = sv; fri[tid] = bi;
        __syncthreads();
        for (int off = 128; off; off >>= 1) {
            if (tid < off) {
                float b2 = frb[tid + off], s2v = frs[tid + off];
                int   i2 = fri[tid + off];
                float b1 = frb[tid], s1v = frs[tid];
                int   i1 = fri[tid];
                if (b2 < b1 || (b2 == b1 && i2 < i1)) {
                    frb[tid] = b2; fri[tid] = i2; frs[tid] = fminf(b1, s2v);
                } else {
                    frs[tid] = fminf(s1v, b2);
                }
            }
            __syncthreads();
        }
        float margin = frs[0] - frb[0];
        int newIdx = fri[0] & (K_CODES - 1);
        __syncthreads();

        // ---- tier 2: compensated exact + window, only for true near-ties ----
        if (!(margin >= 1e-3f)) {           // NaN-safe
            sdd[tid] = (double)xr[tid] * (double)xr[tid];
            __syncthreads();
            for (int off = 128; off; off >>= 1) {
                if (tid < off) sdd[tid] += sdd[tid + off];
                __syncthreads();
            }
            double xn = sdd[0];
            __syncthreads();

            float s[4] = {0.f, 0.f, 0.f, 0.f};
            float c[4] = {0.f, 0.f, 0.f, 0.f};
            #pragma unroll 4
            for (int d = 0; d < DIM; d++) {
                float xv = xr[d];
                float4 ev = *(const float4*)(ebase + (size_t)d * K_CODES);
                float evs[4] = {ev.x, ev.y, ev.z, ev.w};
                #pragma unroll
                for (int j = 0; j < 4; j++) {
                    float p  = xv * evs[j];
                    float e1 = fmaf(xv, evs[j], -p);
                    float t  = s[j] + p;
                    float z  = t - s[j];
                    float e2 = (s[j] - (t - z)) + (p - z);
                    s[j] = t; c[j] += e1 + e2;
                }
            }
            double dist[4];
            #pragma unroll
            for (int j = 0; j < 4; j++)
                dist[j] = xn + g_enorm_d[tid * 4 + j]
                        - 2.0 * ((double)s[j] + (double)c[j]);

            double bv = 1e300; int bi2 = 0x7fffffff;
            #pragma unroll
            for (int j = 0; j < 4; j++) {
                int k = tid * 4 + j;
                if (dist[j] < bv || (dist[j] == bv && k < bi2)) { bv = dist[j]; bi2 = k; }
            }
            svv[tid] = bv; sii[tid] = bi2;
            __syncthreads();
            for (int off = 128; off; off >>= 1) {
                if (tid < off) {
                    double v2 = svv[tid + off]; int i2 = sii[tid + off];
                    if (v2 < svv[tid] || (v2 == svv[tid] && i2 < sii[tid])) {
                        svv[tid] = v2; sii[tid] = i2;
                    }
                }
                __syncthreads();
            }
            if (tid == 0) s_minv = svv[0];
            __syncthreads();
            double minv = s_minv;

            int cand = 0x7fffffff;
            #pragma unroll
            for (int j = 0; j < 4; j++) {
                int k = tid * 4 + j;
                if (dist[j] <= minv + TIE_EPS && k < cand) cand = k;
            }
            sii[tid] = cand;
            __syncthreads();
            for (int off = 128; off; off >>= 1) {
                if (tid < off) { if (sii[tid + off] < sii[tid]) sii[tid] = sii[tid + off]; }
                __syncthreads();
            }
            newIdx = sii[0] & (K_CODES - 1);
            __syncthreads();
        }

        int oldIdx = g_idx[row];
        if (newIdx != oldIdx) {     // uniform across block
            float xv = xr[tid];
            float qn = g_eT[(size_t)newIdx * DIM + tid];
            float qo = g_eT[(size_t)oldIdx * DIM + tid];
            out[(size_t)row * DIM + tid] = xv + (qn - xv);
            double dn = (double)(qn - xv), dl = (double)(qo - xv);
            sdd[tid] = dn * dn - dl * dl;
            __syncthreads();
            for (int off = 128; off; off >>= 1) {
                if (tid < off) sdd[tid] += sdd[tid + off];
                __syncthreads();
            }
            if (tid == 0) atomicAdd(&g_loss_acc, sdd[0]);
        }
        __syncthreads();
    }
}

// ---------------------------------------------------------------------------
__global__ void vq_finish(float* __restrict__ out) {
    const double nd = (double)N_ROWS * (double)DIM;
    out[(size_t)N_ROWS * DIM] = (float)(1.25 * g_loss_acc / nd);
}

// ---------------------------------------------------------------------------
extern "C" void kernel_launch(void* const* d_in, const int* in_sizes, int n_in,
                              void* d_out, int out_size) {
    const float* x = (const float*)d_in[0];
    const float* e = (const float*)d_in[1];
    if (n_in >= 2 && in_sizes[0] == K_CODES * DIM && in_sizes[1] == N_ROWS * DIM) {
        e = (const float*)d_in[0];
        x = (const float*)d_in[1];
    }
    float* out = (float*)d_out;

    cudaFuncSetAttribute(vq_main, cudaFuncAttributeMaxDynamicSharedMemorySize, SMEM_BYTES);

    vq_prep<<<388, 256>>>(e);
    vq_main<<<N_ROWS / BM, 256, SMEM_BYTES>>>(x, out);
    vq_fix<<<2048, 256>>>(x, e, out);
    if (out_size > N_ROWS * DIM) vq_finish<<<1, 1>>>(out);
}